// round 5
// baseline (speedup 1.0000x reference)
#include <cuda_runtime.h>
#include <math.h>

#define H       128
#define TI      24    // interior points per block (3 per warp)
#define TB      32    // boundary points per block
#define THREADS 256
#define PW      3     // points per warp

typedef unsigned long long ull;

// Per-block partial sums (deterministic two-stage reduction; no device mallocs)
__device__ float g_part_int[65536];
__device__ float g_part_bd[8192];

// Accurate tanh independent of -use_fast_math lowering of tanhf.
__device__ __forceinline__ float my_tanh(float x)
{
    float ax = fabsf(x);
    float t  = __expf(-2.0f * ax);
    float r  = (1.0f - t) / (1.0f + t);
    return copysignf(r, x);
}

// ---- packed fp32x2 helpers (sm_103a FFMA2 path) ----
__device__ __forceinline__ void ffma2(ull& acc, ull a, ull w)
{
    asm("fma.rn.f32x2 %0, %1, %2, %0;" : "+l"(acc) : "l"(a), "l"(w));
}
__device__ __forceinline__ ull packf2(float lo, float hi)
{
    ull r;
    asm("mov.b64 %0, {%1, %2};" : "=l"(r) : "f"(lo), "f"(hi));
    return r;
}
__device__ __forceinline__ float foldf2(ull v)
{
    float lo, hi;
    asm("mov.b64 {%0, %1}, %2;" : "=f"(lo), "=f"(hi) : "l"(v));
    return lo + hi;
}

// ---------------------------------------------------------------------------
// Accumulate 4 channels (v, gx, gy, L) x 3 points x 4 units, FFMA2 packed
// along k (even/odd k partial sums, folded exactly at the end).
// Lane t handles units j4 = 4t..4t+3; the warp owns points pp0..pp0+2.
// Activations: lane-uniform LDS.128 (ulonglong2 = two k-pairs); weights:
// warp-contiguous LDG.128 rows, re-packed k-wise (8 mov.b64 per k-group).
// ---------------------------------------------------------------------------
__device__ __forceinline__ void accum4(const float* __restrict__ in,
                                       const float* __restrict__ W,
                                       int j4, int pp0,
                                       float acc[4][PW][4])
{
    ull acc2[4][PW][4];
#pragma unroll
    for (int c = 0; c < 4; c++)
#pragma unroll
        for (int p = 0; p < PW; p++)
#pragma unroll
            for (int u = 0; u < 4; u++) acc2[c][p][u] = 0ULL;

#pragma unroll 1
    for (int k = 0; k < H; k += 4) {
        const float4 w0 = *reinterpret_cast<const float4*>(&W[(k + 0) * H + j4]);
        const float4 w1 = *reinterpret_cast<const float4*>(&W[(k + 1) * H + j4]);
        const float4 w2 = *reinterpret_cast<const float4*>(&W[(k + 2) * H + j4]);
        const float4 w3 = *reinterpret_cast<const float4*>(&W[(k + 3) * H + j4]);

        // k-pairs per unit: w01[u] = (W[k][j4+u], W[k+1][j4+u]), w23 likewise
        ull w01[4], w23[4];
        w01[0] = packf2(w0.x, w1.x); w01[1] = packf2(w0.y, w1.y);
        w01[2] = packf2(w0.z, w1.z); w01[3] = packf2(w0.w, w1.w);
        w23[0] = packf2(w2.x, w3.x); w23[1] = packf2(w2.y, w3.y);
        w23[2] = packf2(w2.z, w3.z); w23[3] = packf2(w2.w, w3.w);

#pragma unroll
        for (int c = 0; c < 4; c++) {
#pragma unroll
            for (int p = 0; p < PW; p++) {
                const ulonglong2 av = *reinterpret_cast<const ulonglong2*>(
                    &in[(c * TI + pp0 + p) * H + k]);
#pragma unroll
                for (int u = 0; u < 4; u++) {
                    ffma2(acc2[c][p][u], av.x, w01[u]);
                    ffma2(acc2[c][p][u], av.y, w23[u]);
                }
            }
        }
    }

#pragma unroll
    for (int c = 0; c < 4; c++)
#pragma unroll
        for (int p = 0; p < PW; p++)
#pragma unroll
            for (int u = 0; u < 4; u++)
                acc[c][p][u] = foldf2(acc2[c][p][u]);
}

// ---------------------------------------------------------------------------
// Interior: 4-channel Taylor-mode Laplacian (v, gx, gy, L = uxx+uyy).
// Warp-autonomous pipeline: no __syncthreads between layers.
// ---------------------------------------------------------------------------
__global__ __launch_bounds__(THREADS, 3)
void pinn_interior(const float* __restrict__ xy, const float* __restrict__ f,
                   const float* __restrict__ W0, const float* __restrict__ b0,
                   const float* __restrict__ W1, const float* __restrict__ b1,
                   const float* __restrict__ W2, const float* __restrict__ b2,
                   const float* __restrict__ W3, int n)
{
    __shared__ float A[4 * TI * H];   // 48 KB, warp-private row blocks

    const int tid  = threadIdx.x;
    const int t    = tid & 31;        // unit group: j = 4t..4t+3
    const int j4   = t * 4;
    const int pp0  = (tid >> 5) * PW; // warp w owns points pp0..pp0+2
    const int base = blockIdx.x * TI;

    // per-warp broadcast loads of this warp's points
    float xin[PW], yin[PW];
#pragma unroll
    for (int p = 0; p < PW; p++) {
        int pt = base + pp0 + p; if (pt > n - 1) pt = n - 1;
        xin[p] = __ldg(&xy[pt * 2 + 0]);
        yin[p] = __ldg(&xy[pt * 2 + 1]);
    }

    // ---- layer 0: (x,y) -> 128 with derivative seeding ----
    {
        const float4 wxv = *reinterpret_cast<const float4*>(&W0[j4]);
        const float4 wyv = *reinterpret_cast<const float4*>(&W0[H + j4]);
        const float4 bbv = *reinterpret_cast<const float4*>(&b0[j4]);
        const float wx[4] = {wxv.x, wxv.y, wxv.z, wxv.w};
        const float wy[4] = {wyv.x, wyv.y, wyv.z, wyv.w};
        const float bj[4] = {bbv.x, bbv.y, bbv.z, bbv.w};
#pragma unroll
        for (int p = 0; p < PW; p++) {
            const int pp = pp0 + p;
            float4 o0, o1, o2, o3;
            float* po0 = &o0.x; float* po1 = &o1.x;
            float* po2 = &o2.x; float* po3 = &o3.x;
#pragma unroll
            for (int u = 0; u < 4; u++) {
                float zv = fmaf(xin[p], wx[u], fmaf(yin[p], wy[u], bj[u]));
                float a  = my_tanh(zv);
                float t1 = 1.0f - a * a;
                float t2 = -2.0f * a * t1;
                po0[u] = a;
                po1[u] = t1 * wx[u];
                po2[u] = t1 * wy[u];
                po3[u] = t2 * fmaf(wx[u], wx[u], wy[u] * wy[u]); // L seed
            }
            *reinterpret_cast<float4*>(&A[(0 * TI + pp) * H + j4]) = o0;
            *reinterpret_cast<float4*>(&A[(1 * TI + pp) * H + j4]) = o1;
            *reinterpret_cast<float4*>(&A[(2 * TI + pp) * H + j4]) = o2;
            *reinterpret_cast<float4*>(&A[(3 * TI + pp) * H + j4]) = o3;
        }
    }
    __syncwarp();

    // ---- layer 1 (in-place: read A, then overwrite A) ----
    {
        float acc[4][PW][4];
        accum4(A, W1, j4, pp0, acc);
        __syncwarp();

        const float4 bb = *reinterpret_cast<const float4*>(&b1[j4]);
        const float bj[4] = {bb.x, bb.y, bb.z, bb.w};
#pragma unroll
        for (int p = 0; p < PW; p++) {
            const int pp = pp0 + p;
            float4 o0, o1, o2, o3;
            float* po0 = &o0.x; float* po1 = &o1.x;
            float* po2 = &o2.x; float* po3 = &o3.x;
#pragma unroll
            for (int u = 0; u < 4; u++) {
                float zv  = acc[0][p][u] + bj[u];
                float zgx = acc[1][p][u];
                float zgy = acc[2][p][u];
                float zL  = acc[3][p][u];
                float a  = my_tanh(zv);
                float t1 = 1.0f - a * a;
                float t2 = -2.0f * a * t1;
                po0[u] = a;
                po1[u] = t1 * zgx;
                po2[u] = t1 * zgy;
                po3[u] = fmaf(t2, fmaf(zgx, zgx, zgy * zgy), t1 * zL);
            }
            *reinterpret_cast<float4*>(&A[(0 * TI + pp) * H + j4]) = o0;
            *reinterpret_cast<float4*>(&A[(1 * TI + pp) * H + j4]) = o1;
            *reinterpret_cast<float4*>(&A[(2 * TI + pp) * H + j4]) = o2;
            *reinterpret_cast<float4*>(&A[(3 * TI + pp) * H + j4]) = o3;
        }
    }
    __syncwarp();

    // ---- layer 2 fused with output projection: lap = W3 . L_out ----
    {
        float acc[4][PW][4];
        accum4(A, W2, j4, pp0, acc);

        const float4 bbv = *reinterpret_cast<const float4*>(&b2[j4]);
        const float4 w3v = *reinterpret_cast<const float4*>(&W3[j4]);
        const float bj[4] = {bbv.x, bbv.y, bbv.z, bbv.w};
        const float w3[4] = {w3v.x, w3v.y, w3v.z, w3v.w};

#pragma unroll
        for (int p = 0; p < PW; p++) {
            float s = 0.0f;
#pragma unroll
            for (int u = 0; u < 4; u++) {
                float zv  = acc[0][p][u] + bj[u];
                float zgx = acc[1][p][u];
                float zgy = acc[2][p][u];
                float zL  = acc[3][p][u];
                float a  = my_tanh(zv);
                float t1 = 1.0f - a * a;
                float t2 = -2.0f * a * t1;
                float L  = fmaf(t2, fmaf(zgx, zgx, zgy * zgy), t1 * zL);
                s = fmaf(L, w3[u], s);
            }
#pragma unroll
            for (int off = 16; off > 0; off >>= 1)
                s += __shfl_xor_sync(0xffffffffu, s, off);
            // stash lap in this warp's (now dead) channel-0 row
            if (t == 0) A[(0 * TI + pp0 + p) * H] = s;
        }
    }
    __syncthreads();   // only block-wide barrier: before final reduction

    if (tid == 0) {
        float ssum = 0.0f;
#pragma unroll
        for (int p = 0; p < TI; p++) {
            int idx = base + p;
            if (idx < n) {
                float d = A[p * H] - f[idx];
                ssum = fmaf(d, d, ssum);
            }
        }
        g_part_int[blockIdx.x] = ssum;
    }
}

// ---------------------------------------------------------------------------
// Boundary: plain forward + squared residual partial sums (small workload).
// ---------------------------------------------------------------------------
__device__ __forceinline__ void hidden1(const float* __restrict__ in,
                                        float* __restrict__ outp,
                                        const float* __restrict__ W,
                                        const float* __restrict__ b,
                                        int j, int p0)
{
    float acc[TB / 2];
#pragma unroll
    for (int p = 0; p < TB / 2; p++) acc[p] = 0.0f;

#pragma unroll 1
    for (int k = 0; k < H; k += 4) {
        const float w0 = W[(k + 0) * H + j];
        const float w1 = W[(k + 1) * H + j];
        const float w2 = W[(k + 2) * H + j];
        const float w3 = W[(k + 3) * H + j];
#pragma unroll
        for (int p = 0; p < TB / 2; p++) {
            const float4 a = *reinterpret_cast<const float4*>(
                &in[(p0 + p) * H + k]);
            acc[p] = fmaf(a.x, w0,
                      fmaf(a.y, w1,
                       fmaf(a.z, w2,
                        fmaf(a.w, w3, acc[p]))));
        }
    }

    const float bj = b[j];
#pragma unroll
    for (int p = 0; p < TB / 2; p++)
        outp[(p0 + p) * H + j] = my_tanh(acc[p] + bj);
}

__global__ __launch_bounds__(THREADS)
void pinn_boundary(const float* __restrict__ xy, const float* __restrict__ g,
                   const float* __restrict__ W0, const float* __restrict__ b0,
                   const float* __restrict__ W1, const float* __restrict__ b1,
                   const float* __restrict__ W2, const float* __restrict__ b2,
                   const float* __restrict__ W3, const float* __restrict__ b3,
                   int n)
{
    __shared__ float A[TB * H];
    __shared__ float B[TB * H];
    __shared__ float sxy[TB * 2];
    __shared__ float red[TB];

    const int tid  = threadIdx.x;
    const int j    = tid & (H - 1);
    const int p0   = (tid >> 7) * (TB / 2);
    const int base = blockIdx.x * TB;

    if (tid < TB * 2) {
        int pt = base + (tid >> 1);
        if (pt > n - 1) pt = n - 1;
        sxy[tid] = xy[pt * 2 + (tid & 1)];
    }
    __syncthreads();

    {
        const float w0x = W0[j];
        const float w0y = W0[H + j];
        const float bj  = b0[j];
#pragma unroll
        for (int p = 0; p < TB / 2; p++) {
            const int pp = p0 + p;
            float x = sxy[pp * 2 + 0];
            float y = sxy[pp * 2 + 1];
            A[pp * H + j] = my_tanh(fmaf(x, w0x, fmaf(y, w0y, bj)));
        }
    }
    __syncthreads();

    hidden1(A, B, W1, b1, j, p0);
    __syncthreads();
    hidden1(B, A, W2, b2, j, p0);
    __syncthreads();

    if (tid < TB) {
        float v = b3[0];
        for (int k = 0; k < H; k++)
            v = fmaf(A[tid * H + k], W3[k], v);
        int idx = base + tid;
        if (idx < n) {
            float d = v - g[idx];
            red[tid] = d * d;
        } else {
            red[tid] = 0.0f;
        }
    }
    __syncthreads();

    if (tid == 0) {
        float s = 0.0f;
#pragma unroll
        for (int p = 0; p < TB; p++) s += red[p];
        g_part_bd[blockIdx.x] = s;
    }
}

// ---------------------------------------------------------------------------
// Final deterministic reduction -> out[0] = loss_bound, out[1] = loss_f
// ---------------------------------------------------------------------------
__global__ __launch_bounds__(THREADS)
void pinn_finalize(float* __restrict__ out, int nbi, int nbb,
                   int n_int, int n_bd)
{
    __shared__ float s[THREADS];
    const int tid = threadIdx.x;

    float a = 0.0f;
    for (int i = tid; i < nbi; i += THREADS) a += g_part_int[i];
    s[tid] = a;
    __syncthreads();
    for (int st = THREADS / 2; st > 0; st >>= 1) {
        if (tid < st) s[tid] += s[tid + st];
        __syncthreads();
    }
    float loss_f = 0.0f;
    if (tid == 0) loss_f = s[0] * (0.5f / (float)n_int);
    __syncthreads();

    float bsm = 0.0f;
    for (int i = tid; i < nbb; i += THREADS) bsm += g_part_bd[i];
    s[tid] = bsm;
    __syncthreads();
    for (int st = THREADS / 2; st > 0; st >>= 1) {
        if (tid < st) s[tid] += s[tid + st];
        __syncthreads();
    }
    if (tid == 0) {
        out[0] = s[0] * (0.5f / (float)n_bd); // loss_bound
        out[1] = loss_f;                      // loss_f
    }
}

// ---------------------------------------------------------------------------
extern "C" void kernel_launch(void* const* d_in, const int* in_sizes, int n_in,
                              void* d_out, int out_size)
{
    const float* xy_int = (const float*)d_in[0];
    const float* f      = (const float*)d_in[1];
    const float* xy_bd  = (const float*)d_in[2];
    const float* g      = (const float*)d_in[3];
    const float* W0     = (const float*)d_in[4];
    const float* b0     = (const float*)d_in[5];
    const float* W1     = (const float*)d_in[6];
    const float* b1     = (const float*)d_in[7];
    const float* W2     = (const float*)d_in[8];
    const float* b2     = (const float*)d_in[9];
    const float* W3     = (const float*)d_in[10];
    const float* b3     = (const float*)d_in[11];

    const int n_int = in_sizes[0] / 2;
    const int n_bd  = in_sizes[2] / 2;

    int gi = (n_int + TI - 1) / TI;
    int gb = (n_bd + TB - 1) / TB;
    if (gi > 65536) gi = 65536; // scratch bound (dataset: 10923)
    if (gb > 8192)  gb = 8192;  // scratch bound (dataset: 512)

    pinn_interior<<<gi, THREADS>>>(xy_int, f, W0, b0, W1, b1, W2, b2, W3,
                                   n_int);
    pinn_boundary<<<gb, THREADS>>>(xy_bd, g, W0, b0, W1, b1, W2, b2, W3, b3,
                                   n_bd);
    pinn_finalize<<<1, THREADS>>>((float*)d_out, gi, gb, n_int, n_bd);
}

// round 6
// speedup vs baseline: 11.8773x; 11.8773x over previous
#include <cuda_runtime.h>
#include <math.h>

#define H       128
#define TI      16    // interior points per block (2 per warp)
#define TB      32    // boundary points per block
#define THREADS 256
#define PW      2     // points per warp

typedef unsigned long long ull;

// Per-block partial sums (deterministic two-stage reduction; no device mallocs)
__device__ float g_part_int[65536];
__device__ float g_part_bd[8192];

// Pre-permuted (k-paired) weights: Wp[kp*H + j] = (W[2kp][j], W[2kp+1][j]).
// Pure permutation (no duplication): 64 KB each, written by a prologue kernel.
__device__ ull g_W1p[(H / 2) * H];
__device__ ull g_W2p[(H / 2) * H];

// Accurate tanh independent of -use_fast_math lowering of tanhf.
__device__ __forceinline__ float my_tanh(float x)
{
    float ax = fabsf(x);
    float t  = __expf(-2.0f * ax);
    float r  = (1.0f - t) / (1.0f + t);
    return copysignf(r, x);
}

// ---- packed fp32x2 helpers (sm_103a FFMA2 path) ----
__device__ __forceinline__ void ffma2(ull& acc, ull a, ull w)
{
    asm("fma.rn.f32x2 %0, %1, %2, %0;" : "+l"(acc) : "l"(a), "l"(w));
}
__device__ __forceinline__ ull packf2(float lo, float hi)
{
    ull r;
    asm("mov.b64 %0, {%1, %2};" : "=l"(r) : "f"(lo), "f"(hi));
    return r;
}
__device__ __forceinline__ float foldf2(ull v)
{
    float lo, hi;
    asm("mov.b64 {%0, %1}, %2;" : "=f"(lo), "=f"(hi) : "l"(v));
    return lo + hi;
}

// ---------------------------------------------------------------------------
// Prologue: permute W[128][128] into k-paired layout (one-time, tiny cost).
// ---------------------------------------------------------------------------
__global__ void pinn_pack(const float* __restrict__ W1,
                          const float* __restrict__ W2)
{
    int i = blockIdx.x * blockDim.x + threadIdx.x;   // over (H/2)*H entries
    if (i < (H / 2) * H) {
        int kp = i / H;
        int j  = i % H;
        g_W1p[i] = packf2(W1[(2 * kp) * H + j], W1[(2 * kp + 1) * H + j]);
        g_W2p[i] = packf2(W2[(2 * kp) * H + j], W2[(2 * kp + 1) * H + j]);
    }
}

// ---------------------------------------------------------------------------
// Accumulate 4 channels (v, gx, gy, L) x 2 points x 4 units with FFMA2,
// paired along k (even/odd partial sums, folded exactly at the end).
// Lane t handles units j4 = 4t..4t+3; the warp owns points pp0, pp0+1.
// Activation k-pairs come free from LDS.128 (ulonglong2); weight k-pairs
// come free from the pre-permuted Wp (warp-contiguous LDG.128).
// ---------------------------------------------------------------------------
__device__ __forceinline__ void accum4(const float* __restrict__ in,
                                       const ull* __restrict__ Wp,
                                       int j4, int pp0,
                                       float acc[4][PW][4])
{
    ull acc2[4][PW][4];
#pragma unroll
    for (int c = 0; c < 4; c++)
#pragma unroll
        for (int p = 0; p < PW; p++)
#pragma unroll
            for (int u = 0; u < 4; u++) acc2[c][p][u] = 0ULL;

#pragma unroll 1
    for (int kp = 0; kp < H / 2; kp += 2) {   // 2 k-pairs = 4 k's per iter
        // weight pairs for units j4..j4+3, k-pairs kp and kp+1
        const ulonglong2 wa = *reinterpret_cast<const ulonglong2*>(
            &Wp[(kp + 0) * H + j4]);
        const ulonglong2 wb = *reinterpret_cast<const ulonglong2*>(
            &Wp[(kp + 0) * H + j4 + 2]);
        const ulonglong2 wc = *reinterpret_cast<const ulonglong2*>(
            &Wp[(kp + 1) * H + j4]);
        const ulonglong2 wd = *reinterpret_cast<const ulonglong2*>(
            &Wp[(kp + 1) * H + j4 + 2]);

#pragma unroll
        for (int c = 0; c < 4; c++) {
#pragma unroll
            for (int p = 0; p < PW; p++) {
                const ulonglong2 av = *reinterpret_cast<const ulonglong2*>(
                    &in[(c * TI + pp0 + p) * H + 2 * kp]);
                ffma2(acc2[c][p][0], av.x, wa.x);
                ffma2(acc2[c][p][1], av.x, wa.y);
                ffma2(acc2[c][p][2], av.x, wb.x);
                ffma2(acc2[c][p][3], av.x, wb.y);
                ffma2(acc2[c][p][0], av.y, wc.x);
                ffma2(acc2[c][p][1], av.y, wc.y);
                ffma2(acc2[c][p][2], av.y, wd.x);
                ffma2(acc2[c][p][3], av.y, wd.y);
            }
        }
    }

#pragma unroll
    for (int c = 0; c < 4; c++)
#pragma unroll
        for (int p = 0; p < PW; p++)
#pragma unroll
            for (int u = 0; u < 4; u++)
                acc[c][p][u] = foldf2(acc2[c][p][u]);
}

// ---------------------------------------------------------------------------
// Interior: 4-channel Taylor-mode Laplacian (v, gx, gy, L = uxx+uyy).
// Warp-autonomous pipeline: no __syncthreads between layers.
// ---------------------------------------------------------------------------
__global__ __launch_bounds__(THREADS, 2)
void pinn_interior(const float* __restrict__ xy, const float* __restrict__ f,
                   const float* __restrict__ W0, const float* __restrict__ b0,
                   const float* __restrict__ b1,
                   const float* __restrict__ b2,
                   const float* __restrict__ W3, int n)
{
    __shared__ __align__(16) float A[4 * TI * H];   // 32 KB

    const int tid  = threadIdx.x;
    const int t    = tid & 31;        // unit group: j = 4t..4t+3
    const int j4   = t * 4;
    const int pp0  = (tid >> 5) * PW; // warp w owns points pp0, pp0+1
    const int base = blockIdx.x * TI;

    // per-warp broadcast loads of this warp's points
    float xin[PW], yin[PW];
#pragma unroll
    for (int p = 0; p < PW; p++) {
        int pt = base + pp0 + p; if (pt > n - 1) pt = n - 1;
        xin[p] = __ldg(&xy[pt * 2 + 0]);
        yin[p] = __ldg(&xy[pt * 2 + 1]);
    }

    // ---- layer 0: (x,y) -> 128 with derivative seeding ----
    {
        const float4 wxv = *reinterpret_cast<const float4*>(&W0[j4]);
        const float4 wyv = *reinterpret_cast<const float4*>(&W0[H + j4]);
        const float4 bbv = *reinterpret_cast<const float4*>(&b0[j4]);
        const float wx[4] = {wxv.x, wxv.y, wxv.z, wxv.w};
        const float wy[4] = {wyv.x, wyv.y, wyv.z, wyv.w};
        const float bj[4] = {bbv.x, bbv.y, bbv.z, bbv.w};
#pragma unroll
        for (int p = 0; p < PW; p++) {
            const int pp = pp0 + p;
            float4 o0, o1, o2, o3;
            float* po0 = &o0.x; float* po1 = &o1.x;
            float* po2 = &o2.x; float* po3 = &o3.x;
#pragma unroll
            for (int u = 0; u < 4; u++) {
                float zv = fmaf(xin[p], wx[u], fmaf(yin[p], wy[u], bj[u]));
                float a  = my_tanh(zv);
                float t1 = 1.0f - a * a;
                float t2 = -2.0f * a * t1;
                po0[u] = a;
                po1[u] = t1 * wx[u];
                po2[u] = t1 * wy[u];
                po3[u] = t2 * fmaf(wx[u], wx[u], wy[u] * wy[u]); // L seed
            }
            *reinterpret_cast<float4*>(&A[(0 * TI + pp) * H + j4]) = o0;
            *reinterpret_cast<float4*>(&A[(1 * TI + pp) * H + j4]) = o1;
            *reinterpret_cast<float4*>(&A[(2 * TI + pp) * H + j4]) = o2;
            *reinterpret_cast<float4*>(&A[(3 * TI + pp) * H + j4]) = o3;
        }
    }
    __syncwarp();

    // ---- layer 1 (in-place: read A, then overwrite A) ----
    {
        float acc[4][PW][4];
        accum4(A, g_W1p, j4, pp0, acc);
        __syncwarp();

        const float4 bb = *reinterpret_cast<const float4*>(&b1[j4]);
        const float bj[4] = {bb.x, bb.y, bb.z, bb.w};
#pragma unroll
        for (int p = 0; p < PW; p++) {
            const int pp = pp0 + p;
            float4 o0, o1, o2, o3;
            float* po0 = &o0.x; float* po1 = &o1.x;
            float* po2 = &o2.x; float* po3 = &o3.x;
#pragma unroll
            for (int u = 0; u < 4; u++) {
                float zv  = acc[0][p][u] + bj[u];
                float zgx = acc[1][p][u];
                float zgy = acc[2][p][u];
                float zL  = acc[3][p][u];
                float a  = my_tanh(zv);
                float t1 = 1.0f - a * a;
                float t2 = -2.0f * a * t1;
                po0[u] = a;
                po1[u] = t1 * zgx;
                po2[u] = t1 * zgy;
                po3[u] = fmaf(t2, fmaf(zgx, zgx, zgy * zgy), t1 * zL);
            }
            *reinterpret_cast<float4*>(&A[(0 * TI + pp) * H + j4]) = o0;
            *reinterpret_cast<float4*>(&A[(1 * TI + pp) * H + j4]) = o1;
            *reinterpret_cast<float4*>(&A[(2 * TI + pp) * H + j4]) = o2;
            *reinterpret_cast<float4*>(&A[(3 * TI + pp) * H + j4]) = o3;
        }
    }
    __syncwarp();

    // ---- layer 2 fused with output projection: lap = W3 . L_out ----
    {
        float acc[4][PW][4];
        accum4(A, g_W2p, j4, pp0, acc);

        const float4 bbv = *reinterpret_cast<const float4*>(&b2[j4]);
        const float4 w3v = *reinterpret_cast<const float4*>(&W3[j4]);
        const float bj[4] = {bbv.x, bbv.y, bbv.z, bbv.w};
        const float w3[4] = {w3v.x, w3v.y, w3v.z, w3v.w};

#pragma unroll
        for (int p = 0; p < PW; p++) {
            float s = 0.0f;
#pragma unroll
            for (int u = 0; u < 4; u++) {
                float zv  = acc[0][p][u] + bj[u];
                float zgx = acc[1][p][u];
                float zgy = acc[2][p][u];
                float zL  = acc[3][p][u];
                float a  = my_tanh(zv);
                float t1 = 1.0f - a * a;
                float t2 = -2.0f * a * t1;
                float L  = fmaf(t2, fmaf(zgx, zgx, zgy * zgy), t1 * zL);
                s = fmaf(L, w3[u], s);
            }
#pragma unroll
            for (int off = 16; off > 0; off >>= 1)
                s += __shfl_xor_sync(0xffffffffu, s, off);
            // stash lap in this warp's (now dead) channel-0 row
            if (t == 0) A[(0 * TI + pp0 + p) * H] = s;
        }
    }
    __syncthreads();   // only block-wide barrier: before final reduction

    if (tid == 0) {
        float ssum = 0.0f;
#pragma unroll
        for (int p = 0; p < TI; p++) {
            int idx = base + p;
            if (idx < n) {
                float d = A[p * H] - f[idx];
                ssum = fmaf(d, d, ssum);
            }
        }
        g_part_int[blockIdx.x] = ssum;
    }
}

// ---------------------------------------------------------------------------
// Boundary: plain forward + squared residual partial sums (small workload).
// ---------------------------------------------------------------------------
__device__ __forceinline__ void hidden1(const float* __restrict__ in,
                                        float* __restrict__ outp,
                                        const float* __restrict__ W,
                                        const float* __restrict__ b,
                                        int j, int p0)
{
    float acc[TB / 2];
#pragma unroll
    for (int p = 0; p < TB / 2; p++) acc[p] = 0.0f;

#pragma unroll 1
    for (int k = 0; k < H; k += 4) {
        const float w0 = W[(k + 0) * H + j];
        const float w1 = W[(k + 1) * H + j];
        const float w2 = W[(k + 2) * H + j];
        const float w3 = W[(k + 3) * H + j];
#pragma unroll
        for (int p = 0; p < TB / 2; p++) {
            const float4 a = *reinterpret_cast<const float4*>(
                &in[(p0 + p) * H + k]);
            acc[p] = fmaf(a.x, w0,
                      fmaf(a.y, w1,
                       fmaf(a.z, w2,
                        fmaf(a.w, w3, acc[p]))));
        }
    }

    const float bj = b[j];
#pragma unroll
    for (int p = 0; p < TB / 2; p++)
        outp[(p0 + p) * H + j] = my_tanh(acc[p] + bj);
}

__global__ __launch_bounds__(THREADS)
void pinn_boundary(const float* __restrict__ xy, const float* __restrict__ g,
                   const float* __restrict__ W0, const float* __restrict__ b0,
                   const float* __restrict__ W1, const float* __restrict__ b1,
                   const float* __restrict__ W2, const float* __restrict__ b2,
                   const float* __restrict__ W3, const float* __restrict__ b3,
                   int n)
{
    __shared__ __align__(16) float A[TB * H];
    __shared__ __align__(16) float B[TB * H];
    __shared__ float sxy[TB * 2];
    __shared__ float red[TB];

    const int tid  = threadIdx.x;
    const int j    = tid & (H - 1);
    const int p0   = (tid >> 7) * (TB / 2);
    const int base = blockIdx.x * TB;

    if (tid < TB * 2) {
        int pt = base + (tid >> 1);
        if (pt > n - 1) pt = n - 1;
        sxy[tid] = xy[pt * 2 + (tid & 1)];
    }
    __syncthreads();

    {
        const float w0x = W0[j];
        const float w0y = W0[H + j];
        const float bj  = b0[j];
#pragma unroll
        for (int p = 0; p < TB / 2; p++) {
            const int pp = p0 + p;
            float x = sxy[pp * 2 + 0];
            float y = sxy[pp * 2 + 1];
            A[pp * H + j] = my_tanh(fmaf(x, w0x, fmaf(y, w0y, bj)));
        }
    }
    __syncthreads();

    hidden1(A, B, W1, b1, j, p0);
    __syncthreads();
    hidden1(B, A, W2, b2, j, p0);
    __syncthreads();

    if (tid < TB) {
        float v = b3[0];
        for (int k = 0; k < H; k++)
            v = fmaf(A[tid * H + k], W3[k], v);
        int idx = base + tid;
        if (idx < n) {
            float d = v - g[idx];
            red[tid] = d * d;
        } else {
            red[tid] = 0.0f;
        }
    }
    __syncthreads();

    if (tid == 0) {
        float s = 0.0f;
#pragma unroll
        for (int p = 0; p < TB; p++) s += red[p];
        g_part_bd[blockIdx.x] = s;
    }
}

// ---------------------------------------------------------------------------
// Final deterministic reduction -> out[0] = loss_bound, out[1] = loss_f
// ---------------------------------------------------------------------------
__global__ __launch_bounds__(THREADS)
void pinn_finalize(float* __restrict__ out, int nbi, int nbb,
                   int n_int, int n_bd)
{
    __shared__ float s[THREADS];
    const int tid = threadIdx.x;

    float a = 0.0f;
    for (int i = tid; i < nbi; i += THREADS) a += g_part_int[i];
    s[tid] = a;
    __syncthreads();
    for (int st = THREADS / 2; st > 0; st >>= 1) {
        if (tid < st) s[tid] += s[tid + st];
        __syncthreads();
    }
    float loss_f = 0.0f;
    if (tid == 0) loss_f = s[0] * (0.5f / (float)n_int);
    __syncthreads();

    float bsm = 0.0f;
    for (int i = tid; i < nbb; i += THREADS) bsm += g_part_bd[i];
    s[tid] = bsm;
    __syncthreads();
    for (int st = THREADS / 2; st > 0; st >>= 1) {
        if (tid < st) s[tid] += s[tid + st];
        __syncthreads();
    }
    if (tid == 0) {
        out[0] = s[0] * (0.5f / (float)n_bd); // loss_bound
        out[1] = loss_f;                      // loss_f
    }
}

// ---------------------------------------------------------------------------
extern "C" void kernel_launch(void* const* d_in, const int* in_sizes, int n_in,
                              void* d_out, int out_size)
{
    const float* xy_int = (const float*)d_in[0];
    const float* f      = (const float*)d_in[1];
    const float* xy_bd  = (const float*)d_in[2];
    const float* g      = (const float*)d_in[3];
    const float* W0     = (const float*)d_in[4];
    const float* b0     = (const float*)d_in[5];
    const float* W1     = (const float*)d_in[6];
    const float* b1     = (const float*)d_in[7];
    const float* W2     = (const float*)d_in[8];
    const float* b2     = (const float*)d_in[9];
    const float* W3     = (const float*)d_in[10];
    const float* b3     = (const float*)d_in[11];

    const int n_int = in_sizes[0] / 2;
    const int n_bd  = in_sizes[2] / 2;

    int gi = (n_int + TI - 1) / TI;
    int gb = (n_bd + TB - 1) / TB;
    if (gi > 65536) gi = 65536; // scratch bound (dataset: 16384)
    if (gb > 8192)  gb = 8192;  // scratch bound (dataset: 512)

    pinn_pack<<<((H / 2) * H + 255) / 256, 256>>>(W1, W2);
    pinn_interior<<<gi, THREADS>>>(xy_int, f, W0, b0, b1, b2, W3, n_int);
    pinn_boundary<<<gb, THREADS>>>(xy_bd, g, W0, b0, W1, b1, W2, b2, W3, b3,
                                   n_bd);
    pinn_finalize<<<1, THREADS>>>((float*)d_out, gi, gb, n_int, n_bd);
}

// round 7
// speedup vs baseline: 14.2131x; 1.1967x over previous
#include <cuda_runtime.h>
#include <math.h>

#define H       128
#define TI      32    // interior points per block (4 per warp, as 2 pairs)
#define NP      (TI / 2)
#define TB      32    // boundary points per block
#define THREADS 256

typedef unsigned long long ull;

// Per-block partial sums (deterministic two-stage reduction; no device mallocs)
__device__ float g_part_int[65536];
__device__ float g_part_bd[8192];

// Accurate tanh independent of -use_fast_math lowering of tanhf.
__device__ __forceinline__ float my_tanh(float x)
{
    float ax = fabsf(x);
    float t  = __expf(-2.0f * ax);
    float r  = (1.0f - t) / (1.0f + t);
    return copysignf(r, x);
}

// ---- packed fp32x2 helpers (sm_103a FFMA2 path) ----
__device__ __forceinline__ void ffma2(ull& acc, ull a, ull w)
{
    asm("fma.rn.f32x2 %0, %1, %2, %0;" : "+l"(acc) : "l"(a), "l"(w));
}
__device__ __forceinline__ ull packf2(float lo, float hi)
{
    ull r;
    asm("mov.b64 %0, {%1, %2};" : "=l"(r) : "f"(lo), "f"(hi));
    return r;
}
__device__ __forceinline__ void unpackf2(ull v, float& lo, float& hi)
{
    asm("mov.b64 {%0, %1}, %2;" : "=f"(lo), "=f"(hi) : "l"(v));
}

// ---------------------------------------------------------------------------
// Accumulate 4 channels x 2 point-pairs x 4 units with point-paired FFMA2.
// Each 64-bit accumulator holds (acc_point0, acc_point1) — per-point math is
// bit-identical to scalar FMA. Activations live in smem as point-pair ulls:
// A2[(c*NP + pq)*H + k] = (a_p0[k], a_p1[k]). Weights: original scalar layout,
// LDG.128 warp-contiguous, duplicated into both halves via 1 MOV per (k,u).
// ---------------------------------------------------------------------------
__device__ __forceinline__ void accum4p(const ull* __restrict__ in,
                                        const float* __restrict__ W,
                                        int j4, int pq0,
                                        ull acc2[4][2][4])
{
#pragma unroll
    for (int c = 0; c < 4; c++)
#pragma unroll
        for (int pr = 0; pr < 2; pr++)
#pragma unroll
            for (int u = 0; u < 4; u++) acc2[c][pr][u] = 0ULL;

#pragma unroll 1
    for (int k = 0; k < H; k += 2) {
        const float4 wA = *reinterpret_cast<const float4*>(&W[(k + 0) * H + j4]);
        const float4 wB = *reinterpret_cast<const float4*>(&W[(k + 1) * H + j4]);
        ull wp0[4], wp1[4];
        wp0[0] = packf2(wA.x, wA.x); wp0[1] = packf2(wA.y, wA.y);
        wp0[2] = packf2(wA.z, wA.z); wp0[3] = packf2(wA.w, wA.w);
        wp1[0] = packf2(wB.x, wB.x); wp1[1] = packf2(wB.y, wB.y);
        wp1[2] = packf2(wB.z, wB.z); wp1[3] = packf2(wB.w, wB.w);

#pragma unroll
        for (int c = 0; c < 4; c++) {
#pragma unroll
            for (int pr = 0; pr < 2; pr++) {
                const ulonglong2 av = *reinterpret_cast<const ulonglong2*>(
                    &in[(c * NP + pq0 + pr) * H + k]);
#pragma unroll
                for (int u = 0; u < 4; u++) {
                    ffma2(acc2[c][pr][u], av.x, wp0[u]);
                    ffma2(acc2[c][pr][u], av.y, wp1[u]);
                }
            }
        }
    }
}

// ---------------------------------------------------------------------------
// Interior: 4-channel Taylor-mode Laplacian (v, gx, gy, L = uxx+uyy),
// point-paired FFMA2, warp-autonomous pipeline.
// ---------------------------------------------------------------------------
__global__ __launch_bounds__(THREADS, 2)
void pinn_interior(const float* __restrict__ xy, const float* __restrict__ f,
                   const float* __restrict__ W0, const float* __restrict__ b0,
                   const float* __restrict__ W1, const float* __restrict__ b1,
                   const float* __restrict__ W2, const float* __restrict__ b2,
                   const float* __restrict__ W3, int n)
{
    extern __shared__ __align__(16) ull A2[];          // 4*NP*H ulls = 64 KB
    float* slap = reinterpret_cast<float*>(A2 + 4 * NP * H);

    const int tid  = threadIdx.x;
    const int t    = tid & 31;        // unit group: j = 4t..4t+3
    const int j4   = t * 4;
    const int w    = tid >> 5;
    const int pq0  = w * 2;           // warp owns pairs pq0, pq0+1 (4 points)
    const int base = blockIdx.x * TI;

    // per-warp broadcast loads of this warp's 4 points
    float xin[4], yin[4];
#pragma unroll
    for (int p = 0; p < 4; p++) {
        int pt = base + pq0 * 2 + p; if (pt > n - 1) pt = n - 1;
        xin[p] = __ldg(&xy[pt * 2 + 0]);
        yin[p] = __ldg(&xy[pt * 2 + 1]);
    }

    // ---- layer 0: (x,y) -> 128 with derivative seeding, pair-packed ----
    {
        const float4 wxv = *reinterpret_cast<const float4*>(&W0[j4]);
        const float4 wyv = *reinterpret_cast<const float4*>(&W0[H + j4]);
        const float4 bbv = *reinterpret_cast<const float4*>(&b0[j4]);
        const float wx[4] = {wxv.x, wxv.y, wxv.z, wxv.w};
        const float wy[4] = {wyv.x, wyv.y, wyv.z, wyv.w};
        const float bj[4] = {bbv.x, bbv.y, bbv.z, bbv.w};
#pragma unroll
        for (int pr = 0; pr < 2; pr++) {
            const int pq = pq0 + pr;
            ull o[4][4];   // [channel][unit] pair values
#pragma unroll
            for (int half = 0; half < 2; half++) {
                const float x = xin[pr * 2 + half];
                const float y = yin[pr * 2 + half];
#pragma unroll
                for (int u = 0; u < 4; u++) {
                    float zv = fmaf(x, wx[u], fmaf(y, wy[u], bj[u]));
                    float a  = my_tanh(zv);
                    float t1 = 1.0f - a * a;
                    float t2 = -2.0f * a * t1;
                    float vv[4];
                    vv[0] = a;
                    vv[1] = t1 * wx[u];
                    vv[2] = t1 * wy[u];
                    vv[3] = t2 * fmaf(wx[u], wx[u], wy[u] * wy[u]);
#pragma unroll
                    for (int c = 0; c < 4; c++) {
                        if (half == 0) o[c][u] = packf2(vv[c], 0.0f);
                        else {
                            float lo, dead;
                            unpackf2(o[c][u], lo, dead);
                            o[c][u] = packf2(lo, vv[c]);
                        }
                    }
                }
            }
#pragma unroll
            for (int c = 0; c < 4; c++) {
                *reinterpret_cast<ulonglong2*>(&A2[(c * NP + pq) * H + j4]) =
                    make_ulonglong2(o[c][0], o[c][1]);
                *reinterpret_cast<ulonglong2*>(&A2[(c * NP + pq) * H + j4 + 2]) =
                    make_ulonglong2(o[c][2], o[c][3]);
            }
        }
    }
    __syncwarp();

    // ---- layer 1 (in-place: read A2, then overwrite A2) ----
    {
        ull acc2[4][2][4];
        accum4p(A2, W1, j4, pq0, acc2);
        __syncwarp();

        const float4 bb = *reinterpret_cast<const float4*>(&b1[j4]);
        const float bj[4] = {bb.x, bb.y, bb.z, bb.w};
#pragma unroll
        for (int pr = 0; pr < 2; pr++) {
            const int pq = pq0 + pr;
            ull o[4][4];
#pragma unroll
            for (int u = 0; u < 4; u++) {
                float zv0, zv1, gx0, gx1, gy0, gy1, zL0, zL1;
                unpackf2(acc2[0][pr][u], zv0, zv1);
                unpackf2(acc2[1][pr][u], gx0, gx1);
                unpackf2(acc2[2][pr][u], gy0, gy1);
                unpackf2(acc2[3][pr][u], zL0, zL1);

                float a0  = my_tanh(zv0 + bj[u]);
                float t10 = 1.0f - a0 * a0;
                float t20 = -2.0f * a0 * t10;
                float a1  = my_tanh(zv1 + bj[u]);
                float t11 = 1.0f - a1 * a1;
                float t21 = -2.0f * a1 * t11;

                o[0][u] = packf2(a0, a1);
                o[1][u] = packf2(t10 * gx0, t11 * gx1);
                o[2][u] = packf2(t10 * gy0, t11 * gy1);
                o[3][u] = packf2(
                    fmaf(t20, fmaf(gx0, gx0, gy0 * gy0), t10 * zL0),
                    fmaf(t21, fmaf(gx1, gx1, gy1 * gy1), t11 * zL1));
            }
#pragma unroll
            for (int c = 0; c < 4; c++) {
                *reinterpret_cast<ulonglong2*>(&A2[(c * NP + pq) * H + j4]) =
                    make_ulonglong2(o[c][0], o[c][1]);
                *reinterpret_cast<ulonglong2*>(&A2[(c * NP + pq) * H + j4 + 2]) =
                    make_ulonglong2(o[c][2], o[c][3]);
            }
        }
    }
    __syncwarp();

    // ---- layer 2 fused with output projection: lap = W3 . L_out ----
    {
        ull acc2[4][2][4];
        accum4p(A2, W2, j4, pq0, acc2);

        const float4 bbv = *reinterpret_cast<const float4*>(&b2[j4]);
        const float4 w3v = *reinterpret_cast<const float4*>(&W3[j4]);
        const float bj[4] = {bbv.x, bbv.y, bbv.z, bbv.w};
        const float w3[4] = {w3v.x, w3v.y, w3v.z, w3v.w};

#pragma unroll
        for (int pr = 0; pr < 2; pr++) {
            float s0 = 0.0f, s1 = 0.0f;
#pragma unroll
            for (int u = 0; u < 4; u++) {
                float zv0, zv1, gx0, gx1, gy0, gy1, zL0, zL1;
                unpackf2(acc2[0][pr][u], zv0, zv1);
                unpackf2(acc2[1][pr][u], gx0, gx1);
                unpackf2(acc2[2][pr][u], gy0, gy1);
                unpackf2(acc2[3][pr][u], zL0, zL1);

                float a0  = my_tanh(zv0 + bj[u]);
                float t10 = 1.0f - a0 * a0;
                float t20 = -2.0f * a0 * t10;
                float L0  = fmaf(t20, fmaf(gx0, gx0, gy0 * gy0), t10 * zL0);
                s0 = fmaf(L0, w3[u], s0);

                float a1  = my_tanh(zv1 + bj[u]);
                float t11 = 1.0f - a1 * a1;
                float t21 = -2.0f * a1 * t11;
                float L1  = fmaf(t21, fmaf(gx1, gx1, gy1 * gy1), t11 * zL1);
                s1 = fmaf(L1, w3[u], s1);
            }
#pragma unroll
            for (int off = 16; off > 0; off >>= 1) {
                s0 += __shfl_xor_sync(0xffffffffu, s0, off);
                s1 += __shfl_xor_sync(0xffffffffu, s1, off);
            }
            if (t == 0) {
                slap[(pq0 + pr) * 2 + 0] = s0;
                slap[(pq0 + pr) * 2 + 1] = s1;
            }
        }
    }
    __syncthreads();   // only block-wide barrier: before final reduction

    if (tid == 0) {
        float ssum = 0.0f;
#pragma unroll
        for (int p = 0; p < TI; p++) {
            int idx = base + p;
            if (idx < n) {
                float d = slap[p] - f[idx];
                ssum = fmaf(d, d, ssum);
            }
        }
        g_part_int[blockIdx.x] = ssum;
    }
}

// ---------------------------------------------------------------------------
// Boundary: plain forward + squared residual partial sums (small workload).
// ---------------------------------------------------------------------------
__device__ __forceinline__ void hidden1(const float* __restrict__ in,
                                        float* __restrict__ outp,
                                        const float* __restrict__ W,
                                        const float* __restrict__ b,
                                        int j, int p0)
{
    float acc[TB / 2];
#pragma unroll
    for (int p = 0; p < TB / 2; p++) acc[p] = 0.0f;

#pragma unroll 1
    for (int k = 0; k < H; k += 4) {
        const float w0 = W[(k + 0) * H + j];
        const float w1 = W[(k + 1) * H + j];
        const float w2 = W[(k + 2) * H + j];
        const float w3 = W[(k + 3) * H + j];
#pragma unroll
        for (int p = 0; p < TB / 2; p++) {
            const float4 a = *reinterpret_cast<const float4*>(
                &in[(p0 + p) * H + k]);
            acc[p] = fmaf(a.x, w0,
                      fmaf(a.y, w1,
                       fmaf(a.z, w2,
                        fmaf(a.w, w3, acc[p]))));
        }
    }

    const float bj = b[j];
#pragma unroll
    for (int p = 0; p < TB / 2; p++)
        outp[(p0 + p) * H + j] = my_tanh(acc[p] + bj);
}

__global__ __launch_bounds__(THREADS)
void pinn_boundary(const float* __restrict__ xy, const float* __restrict__ g,
                   const float* __restrict__ W0, const float* __restrict__ b0,
                   const float* __restrict__ W1, const float* __restrict__ b1,
                   const float* __restrict__ W2, const float* __restrict__ b2,
                   const float* __restrict__ W3, const float* __restrict__ b3,
                   int n)
{
    __shared__ __align__(16) float A[TB * H];
    __shared__ __align__(16) float B[TB * H];
    __shared__ float sxy[TB * 2];
    __shared__ float red[TB];

    const int tid  = threadIdx.x;
    const int j    = tid & (H - 1);
    const int p0   = (tid >> 7) * (TB / 2);
    const int base = blockIdx.x * TB;

    if (tid < TB * 2) {
        int pt = base + (tid >> 1);
        if (pt > n - 1) pt = n - 1;
        sxy[tid] = xy[pt * 2 + (tid & 1)];
    }
    __syncthreads();

    {
        const float w0x = W0[j];
        const float w0y = W0[H + j];
        const float bj  = b0[j];
#pragma unroll
        for (int p = 0; p < TB / 2; p++) {
            const int pp = p0 + p;
            float x = sxy[pp * 2 + 0];
            float y = sxy[pp * 2 + 1];
            A[pp * H + j] = my_tanh(fmaf(x, w0x, fmaf(y, w0y, bj)));
        }
    }
    __syncthreads();

    hidden1(A, B, W1, b1, j, p0);
    __syncthreads();
    hidden1(B, A, W2, b2, j, p0);
    __syncthreads();

    if (tid < TB) {
        float v = b3[0];
        for (int k = 0; k < H; k++)
            v = fmaf(A[tid * H + k], W3[k], v);
        int idx = base + tid;
        if (idx < n) {
            float d = v - g[idx];
            red[tid] = d * d;
        } else {
            red[tid] = 0.0f;
        }
    }
    __syncthreads();

    if (tid == 0) {
        float s = 0.0f;
#pragma unroll
        for (int p = 0; p < TB; p++) s += red[p];
        g_part_bd[blockIdx.x] = s;
    }
}

// ---------------------------------------------------------------------------
// Final deterministic reduction -> out[0] = loss_bound, out[1] = loss_f
// ---------------------------------------------------------------------------
__global__ __launch_bounds__(THREADS)
void pinn_finalize(float* __restrict__ out, int nbi, int nbb,
                   int n_int, int n_bd)
{
    __shared__ float s[THREADS];
    const int tid = threadIdx.x;

    float a = 0.0f;
    for (int i = tid; i < nbi; i += THREADS) a += g_part_int[i];
    s[tid] = a;
    __syncthreads();
    for (int st = THREADS / 2; st > 0; st >>= 1) {
        if (tid < st) s[tid] += s[tid + st];
        __syncthreads();
    }
    float loss_f = 0.0f;
    if (tid == 0) loss_f = s[0] * (0.5f / (float)n_int);
    __syncthreads();

    float bsm = 0.0f;
    for (int i = tid; i < nbb; i += THREADS) bsm += g_part_bd[i];
    s[tid] = bsm;
    __syncthreads();
    for (int st = THREADS / 2; st > 0; st >>= 1) {
        if (tid < st) s[tid] += s[tid + st];
        __syncthreads();
    }
    if (tid == 0) {
        out[0] = s[0] * (0.5f / (float)n_bd); // loss_bound
        out[1] = loss_f;                      // loss_f
    }
}

// ---------------------------------------------------------------------------
extern "C" void kernel_launch(void* const* d_in, const int* in_sizes, int n_in,
                              void* d_out, int out_size)
{
    const float* xy_int = (const float*)d_in[0];
    const float* f      = (const float*)d_in[1];
    const float* xy_bd  = (const float*)d_in[2];
    const float* g      = (const float*)d_in[3];
    const float* W0     = (const float*)d_in[4];
    const float* b0     = (const float*)d_in[5];
    const float* W1     = (const float*)d_in[6];
    const float* b1     = (const float*)d_in[7];
    const float* W2     = (const float*)d_in[8];
    const float* b2     = (const float*)d_in[9];
    const float* W3     = (const float*)d_in[10];
    const float* b3     = (const float*)d_in[11];

    const int n_int = in_sizes[0] / 2;
    const int n_bd  = in_sizes[2] / 2;

    int gi = (n_int + TI - 1) / TI;
    int gb = (n_bd + TB - 1) / TB;
    if (gi > 65536) gi = 65536; // scratch bound (dataset: 8192)
    if (gb > 8192)  gb = 8192;  // scratch bound (dataset: 512)

    // dynamic smem: pair-packed activations + lap scratch
    const int smem_bytes = 4 * NP * H * (int)sizeof(ull)
                         + TI * (int)sizeof(float);   // 65664 B

    cudaFuncSetAttribute(pinn_interior,
                         cudaFuncAttributeMaxDynamicSharedMemorySize,
                         smem_bytes);

    pinn_interior<<<gi, THREADS, smem_bytes>>>(xy_int, f, W0, b0, W1, b1,
                                               W2, b2, W3, n_int);
    pinn_boundary<<<gb, THREADS>>>(xy_bd, g, W0, b0, W1, b1, W2, b2, W3, b3,
                                   n_bd);
    pinn_finalize<<<1, THREADS>>>((float*)d_out, gi, gb, n_int, n_bd);
}